// round 1
// baseline (speedup 1.0000x reference)
#include <cuda_runtime.h>
#include <cstdint>

#define BB 4
#define DD 48
#define HHH 48
#define WWW 48
#define AAN 3
#define GG 8
#define NVOX (DD*HHH*WWW)      /* 110592 */
#define NELEM (NVOX*AAN)       /* 331776 */
#define KTOP 800

// ---------------- device scratch (static, allocation-free) ----------------
__device__ unsigned g_u[BB*NELEM];          // order-mapped conf for negatives, 0 otherwise
__device__ unsigned g_hist1[BB][2048];
__device__ unsigned g_hist2[BB][2048];
__device__ unsigned g_hist3[BB][1024];
__device__ float    g_pos_sum[BB];
__device__ float    g_reg_sum[BB];
__device__ unsigned g_npos[BB];
__device__ float    g_topsum[BB];
__device__ int      g_done[BB];
__device__ int      g_b1[BB], g_b2[BB];
__device__ unsigned g_k2[BB], g_k3[BB];
__device__ float    g_kcnt[BB];

// ---------------- helpers ----------------
__device__ __forceinline__ float softplus0(float x) {      // bce(x, y=0)
    return fmaxf(x, 0.0f) + log1pf(expf(-fabsf(x)));
}
__device__ __forceinline__ float sl1(float x) {
    float ax = fabsf(x);
    return (ax < 1.0f) ? 0.5f * x * x : ax - 0.5f;
}
__device__ __forceinline__ unsigned ordmap(float f) {      // monotone float->uint
    unsigned b = __float_as_uint(f);
    return (b & 0x80000000u) ? ~b : (b | 0x80000000u);
}
__device__ __forceinline__ float unord(unsigned u) {
    unsigned b = (u & 0x80000000u) ? (u ^ 0x80000000u) : ~u;
    return __uint_as_float(b);
}

// ---------------- kernel 0: zero accumulators/histograms ----------------
__global__ void k_init() {
    int i = blockIdx.x * blockDim.x + threadIdx.x;
    unsigned* h1 = &g_hist1[0][0];
    unsigned* h2 = &g_hist2[0][0];
    unsigned* h3 = &g_hist3[0][0];
    if (i < BB * 2048) { h1[i] = 0u; h2[i] = 0u; }
    if (i < BB * 1024) h3[i] = 0u;
    if (i < BB) {
        g_pos_sum[i] = 0.f; g_reg_sum[i] = 0.f; g_topsum[i] = 0.f;
        g_npos[i] = 0u; g_done[i] = 0; g_kcnt[i] = 0.f;
    }
}

// ---------------- kernel 1: main pass ----------------
// one thread per voxel (handles all 3 anchors); grid (NVOX/256, B)
__global__ void k_main(const float* __restrict__ pred, const float* __restrict__ tgt) {
    __shared__ float s_gxp[GG], s_gxm[GG], s_gyp[GG], s_gym[GG], s_gzp[GG], s_gzm[GG];
    __shared__ float s_gx[GG], s_gy[GG], s_gz[GG], s_gd[GG], s_d3[GG];
    __shared__ unsigned s_hist[2048];

    const int b = blockIdx.y;
    const int tid = threadIdx.x;
    if (tid < GG) {
        const float* t = tgt + (b * GG + tid) * 4;
        float gx = t[0], gy = t[1], gz = t[2], gd = t[3];
        float r2 = 0.5f * gd;
        s_gx[tid] = gx; s_gy[tid] = gy; s_gz[tid] = gz; s_gd[tid] = gd;
        s_gxp[tid] = gx + r2; s_gxm[tid] = gx - r2;
        s_gyp[tid] = gy + r2; s_gym[tid] = gy - r2;
        s_gzp[tid] = gz + r2; s_gzm[tid] = gz - r2;
        s_d3[tid] = gd * gd * gd;
    }
    for (int i = tid; i < 2048; i += blockDim.x) s_hist[i] = 0u;
    __syncthreads();

    const int vox = blockIdx.x * blockDim.x + tid;
    const int w = vox % WWW;
    const int t2 = vox / WWW;
    const int h = t2 % HHH;
    const int d = t2 / HHH;
    const float cx = (float)(w * 4 + 2);
    const float cy = (float)(h * 4 + 2);
    const float cz = (float)(d * 4 + 2);

    const float* p = pred + ((size_t)b * NELEM + (size_t)vox * AAN) * 5;

    const float r1s[3]  = {2.5f, 5.0f, 10.0f};
    const float a3s[3]  = {125.0f, 1000.0f, 8000.0f};
    const float inva[3] = {0.2f, 0.1f, 0.05f};

    float bi[3], bu[3];
    int   bidx[3];
#pragma unroll
    for (int a = 0; a < 3; a++) { bi[a] = -1.0f; bu[a] = 1.0f; bidx[a] = 0; }

#pragma unroll
    for (int g = 0; g < GG; g++) {
        float xp = s_gxp[g], xm = s_gxm[g];
        float yp = s_gyp[g], ym = s_gym[g];
        float zp = s_gzp[g], zm = s_gzm[g];
        float d3 = s_d3[g];
#pragma unroll
        for (int a = 0; a < 3; a++) {
            float r1 = r1s[a];
            float ix = fminf(cx + r1, xp) - fmaxf(cx - r1, xm); ix = fmaxf(ix, 0.0f);
            float iy = fminf(cy + r1, yp) - fmaxf(cy - r1, ym); iy = fmaxf(iy, 0.0f);
            float iz = fminf(cz + r1, zp) - fmaxf(cz - r1, zm); iz = fmaxf(iz, 0.0f);
            float inter = ix * iy * iz;
            float un = a3s[a] + d3 - inter + 1e-6f;
            // iou_g > iou_best  <=>  inter*bu > bi*un  (both denominators > 0)
            if (inter * bu[a] > bi[a] * un) { bi[a] = inter; bu[a] = un; bidx[a] = g; }
        }
    }

    unsigned uout[3];
    float lpos = 0.0f, lreg = 0.0f;
    int lnp = 0;
#pragma unroll
    for (int a = 0; a < 3; a++) {
        float conf = p[a * 5];
        bool pos = bi[a] > 0.5f  * bu[a];
        bool neg = bi[a] < 0.02f * bu[a];
        unsigned u = 0u;
        if (neg) { u = ordmap(conf); atomicAdd(&s_hist[u >> 21], 1u); }
        uout[a] = u;
        if (pos) {
            lnp++;
            lpos += fmaxf(conf, 0.0f) - conf + log1pf(expf(-fabsf(conf)));
            int g = bidx[a];
            float ia = inva[a];
            float tx = (s_gx[g] - cx) * ia;
            float ty = (s_gy[g] - cy) * ia;
            float tz = (s_gz[g] - cz) * ia;
            float td = logf(s_gd[g] * ia);
            lreg += sl1(p[a*5+1] - tx) + sl1(p[a*5+2] - ty)
                  + sl1(p[a*5+3] - tz) + sl1(p[a*5+4] - td);
        }
    }
    unsigned base = (unsigned)b * NELEM + (unsigned)vox * 3u;
    g_u[base]     = uout[0];
    g_u[base + 1] = uout[1];
    g_u[base + 2] = uout[2];
    if (lnp) {
        atomicAdd(&g_pos_sum[b], lpos);
        atomicAdd(&g_reg_sum[b], lreg);
        atomicAdd(&g_npos[b], (unsigned)lnp);
    }
    __syncthreads();
    for (int i = tid; i < 2048; i += blockDim.x) {
        unsigned c = s_hist[i];
        if (c) atomicAdd(&g_hist1[b][i], c);
    }
}

// ---------------- kernel 2: level-1 select (1 warp per sample) ----------------
__global__ void k_sel1() {
    const int lane = threadIdx.x & 31;
    const int b = threadIdx.x >> 5;
    if (b >= BB) return;
    const unsigned* h = g_hist1[b];
    const int base = 2047 - 64 * lane;      // lane 0 covers the top bins
    unsigned cc = 0;
#pragma unroll 8
    for (int j = 0; j < 64; j++) cc += h[base - j];
    unsigned pre = cc;
#pragma unroll
    for (int off = 1; off < 32; off <<= 1) {
        unsigned v = __shfl_up_sync(0xffffffffu, pre, off);
        if (lane >= off) pre += v;
    }
    const unsigned excl = pre - cc;
    const unsigned total = __shfl_sync(0xffffffffu, pre, 31);
    if (total <= KTOP) {
        if (lane == 0) { g_done[b] = 1; g_kcnt[b] = (float)total; }
        return;
    }
    if (lane == 0) { g_done[b] = 0; g_kcnt[b] = (float)KTOP; }
    bool cross = (excl < KTOP) && (pre >= KTOP);
    unsigned m = __ballot_sync(0xffffffffu, cross);
    int src = __ffs(m) - 1;
    if (lane == src) {
        unsigned c = excl;
        for (int j = 0; j < 64; j++) {
            unsigned cnt = h[base - j];
            if (c + cnt >= KTOP) { g_b1[b] = base - j; g_k2[b] = KTOP - c; break; }
            c += cnt;
        }
    }
}

// ---------------- kernel 3: refine level 2 ----------------
// strictly-above-bin1 elements: accumulate softplus sum; in-bin elements: hist2
__global__ void k_refine2() {
    const int b = blockIdx.y;
    const int i = blockIdx.x * blockDim.x + threadIdx.x;
    const uint4 v = ((const uint4*)g_u)[(size_t)b * (NELEM / 4) + i];
    const int done = g_done[b];
    const int b1 = g_b1[b];
    unsigned uu[4] = {v.x, v.y, v.z, v.w};
    float s = 0.0f;
#pragma unroll
    for (int j = 0; j < 4; j++) {
        unsigned u = uu[j];
        if (!u) continue;
        if (done) {
            s += softplus0(unord(u));
        } else {
            int t = (int)(u >> 21);
            if (t > b1) s += softplus0(unord(u));
            else if (t == b1) atomicAdd(&g_hist2[b][(u >> 10) & 0x7FFu], 1u);
        }
    }
#pragma unroll
    for (int off = 16; off; off >>= 1) s += __shfl_down_sync(0xffffffffu, s, off);
    if ((threadIdx.x & 31) == 0 && s != 0.0f) atomicAdd(&g_topsum[b], s);
}

// ---------------- kernel 4: level-2 select ----------------
__global__ void k_sel2() {
    const int lane = threadIdx.x & 31;
    const int b = threadIdx.x >> 5;
    if (b >= BB) return;
    if (g_done[b]) return;
    const unsigned k = g_k2[b];
    const unsigned* h = g_hist2[b];
    const int base = 2047 - 64 * lane;
    unsigned cc = 0;
#pragma unroll 8
    for (int j = 0; j < 64; j++) cc += h[base - j];
    unsigned pre = cc;
#pragma unroll
    for (int off = 1; off < 32; off <<= 1) {
        unsigned v = __shfl_up_sync(0xffffffffu, pre, off);
        if (lane >= off) pre += v;
    }
    const unsigned excl = pre - cc;
    bool cross = (excl < k) && (pre >= k);
    unsigned m = __ballot_sync(0xffffffffu, cross);
    int src = __ffs(m) - 1;
    if (lane == src) {
        unsigned c = excl;
        for (int j = 0; j < 64; j++) {
            unsigned cnt = h[base - j];
            if (c + cnt >= k) { g_b2[b] = base - j; g_k3[b] = k - c; break; }
            c += cnt;
        }
    }
}

// ---------------- kernel 5: refine level 3 ----------------
__global__ void k_refine3() {
    const int b = blockIdx.y;
    if (g_done[b]) return;
    const int i = blockIdx.x * blockDim.x + threadIdx.x;
    const uint4 v = ((const uint4*)g_u)[(size_t)b * (NELEM / 4) + i];
    const int b1 = g_b1[b];
    const int b2 = g_b2[b];
    unsigned uu[4] = {v.x, v.y, v.z, v.w};
    float s = 0.0f;
#pragma unroll
    for (int j = 0; j < 4; j++) {
        unsigned u = uu[j];
        if (!u) continue;
        if ((int)(u >> 21) != b1) continue;
        int m = (int)((u >> 10) & 0x7FFu);
        if (m > b2) s += softplus0(unord(u));
        else if (m == b2) atomicAdd(&g_hist3[b][u & 0x3FFu], 1u);
    }
#pragma unroll
    for (int off = 16; off; off >>= 1) s += __shfl_down_sync(0xffffffffu, s, off);
    if ((threadIdx.x & 31) == 0 && s != 0.0f) atomicAdd(&g_topsum[b], s);
}

// ---------------- kernel 6: level-3 select (exact values) + finalize ----------------
__global__ void k_final(float* __restrict__ out) {
    __shared__ float s_neg[BB];
    const int lane = threadIdx.x & 31;
    const int b = threadIdx.x >> 5;
    if (b < BB) {
        float negl = 0.0f;
        const float kcnt = g_kcnt[b];
        if (g_done[b]) {
            if (lane == 0) negl = (kcnt > 0.0f) ? g_topsum[b] / kcnt : 0.0f;
        } else {
            const unsigned k = g_k3[b];
            const unsigned pref = ((unsigned)g_b1[b] << 21) | ((unsigned)g_b2[b] << 10);
            const unsigned* h = g_hist3[b];
            const int base = 1023 - 32 * lane;
            unsigned cc = 0;
            float ws = 0.0f;
            for (int j = 0; j < 32; j++) {
                unsigned cnt = h[base - j];
                if (cnt) ws += (float)cnt * softplus0(unord(pref | (unsigned)(base - j)));
                cc += cnt;
            }
            unsigned pre = cc;
#pragma unroll
            for (int off = 1; off < 32; off <<= 1) {
                unsigned v = __shfl_up_sync(0xffffffffu, pre, off);
                if (lane >= off) pre += v;
            }
            const unsigned excl = pre - cc;
            float contrib;
            if (pre <= k) contrib = ws;          // whole chunk included
            else if (excl >= k) contrib = 0.0f;  // whole chunk excluded
            else {                               // crossing chunk: partial walk
                unsigned c = excl;
                contrib = 0.0f;
                for (int j = 0; j < 32; j++) {
                    unsigned cnt = h[base - j];
                    if (!cnt) continue;
                    float sp = softplus0(unord(pref | (unsigned)(base - j)));
                    if (c + cnt >= k) { contrib += (float)(k - c) * sp; break; }
                    contrib += (float)cnt * sp;
                    c += cnt;
                }
            }
#pragma unroll
            for (int off = 16; off; off >>= 1)
                contrib += __shfl_down_sync(0xffffffffu, contrib, off);
            if (lane == 0) negl = (g_topsum[b] + contrib) / kcnt;
        }
        if (lane == 0) s_neg[b] = negl;
    }
    __syncthreads();
    if (threadIdx.x == 0) {
        float cls = 0.0f, reg = 0.0f, npsum = 0.0f;
        for (int bb = 0; bb < BB; bb++) {
            float np = (float)g_npos[bb];
            float pl = (np > 0.0f) ? 5.0f * g_pos_sum[bb] / np : 0.0f;
            float rl = (np > 0.0f) ? g_reg_sum[bb] / (4.0f * np) : 0.0f;
            cls += pl + s_neg[bb];
            reg += rl;
            npsum += np;
        }
        cls *= 0.25f;
        reg *= 0.25f;
        out[0] = cls + 0.5f * reg;
        out[1] = cls;
        out[2] = reg;
        out[3] = npsum;
    }
}

// ---------------- launcher ----------------
extern "C" void kernel_launch(void* const* d_in, const int* in_sizes, int n_in,
                              void* d_out, int out_size) {
    const float* pred = (const float*)d_in[0];   // (4,48,48,48,3,5)
    const float* tgt  = (const float*)d_in[1];   // (4,8,4)
    float* out = (float*)d_out;

    k_init<<<32, 256>>>();
    dim3 gm(NVOX / 256, BB);
    k_main<<<gm, 256>>>(pred, tgt);
    k_sel1<<<1, 128>>>();
    dim3 gr(NELEM / 4 / 256, BB);   // 324 x 4
    k_refine2<<<gr, 256>>>();
    k_sel2<<<1, 128>>>();
    k_refine3<<<gr, 256>>>();
    k_final<<<1, 128>>>(out);
}

// round 2
// speedup vs baseline: 1.0935x; 1.0935x over previous
#include <cuda_runtime.h>
#include <cstdint>

#define BB 4
#define DD 48
#define HHH 48
#define WWW 48
#define AAN 3
#define GG 8
#define NVOX (DD*HHH*WWW)      /* 110592 */
#define NELEM (NVOX*AAN)       /* 331776 */
#define KTOP 800

// ---------------- device scratch (static, zero-initialized, self-cleaning) ----
__device__ unsigned g_u[BB*NELEM];       // order-mapped conf for negatives, 0 otherwise
__device__ unsigned g_list[BB*NELEM];    // compacted crossing-bin elements
__device__ unsigned g_hist1[BB][2048];
__device__ float    g_pos_sum[BB];
__device__ float    g_reg_sum[BB];
__device__ float    g_topsum[BB];
__device__ float    g_neg[BB];
__device__ float    g_kcnt[BB];
__device__ unsigned g_npos[BB];
__device__ unsigned g_k2[BB];
__device__ unsigned g_listn[BB];
__device__ int      g_done[BB];
__device__ int      g_b1[BB];
__device__ unsigned g_arriveA[BB];
__device__ unsigned g_arriveB[BB];
__device__ unsigned g_arriveF;

// ---------------- helpers ----------------
__device__ __forceinline__ float softplus0(float x) {      // bce(x, y=0)
    return fmaxf(x, 0.0f) + log1pf(expf(-fabsf(x)));
}
__device__ __forceinline__ float sl1(float x) {
    float ax = fabsf(x);
    return (ax < 1.0f) ? 0.5f * x * x : ax - 0.5f;
}
__device__ __forceinline__ unsigned ordmap(float f) {      // monotone float->uint
    unsigned b = __float_as_uint(f);
    return (b & 0x80000000u) ? ~b : (b | 0x80000000u);
}
__device__ __forceinline__ float unord(unsigned u) {
    unsigned b = (u & 0x80000000u) ? (u ^ 0x80000000u) : ~u;
    return __uint_as_float(b);
}
__device__ __forceinline__ unsigned wscan_incl(unsigned v) {
    int lane = threadIdx.x & 31;
#pragma unroll
    for (int o = 1; o < 32; o <<= 1) {
        unsigned t = __shfl_up_sync(0xffffffffu, v, o);
        if (lane >= o) v += t;
    }
    return v;
}

// ================= kernel A: main pass + fused level-1 selection =============
// one thread per voxel (handles all 3 anchors); grid (NVOX/256, BB)
__global__ void k_A(const float* __restrict__ pred, const float* __restrict__ tgt) {
    __shared__ float s_gxp[GG], s_gxm[GG], s_gyp[GG], s_gym[GG], s_gzp[GG], s_gzm[GG];
    __shared__ float s_gx[GG], s_gy[GG], s_gz[GG], s_gd[GG], s_d3[GG];
    __shared__ unsigned s_hist[2048];
    __shared__ int s_last;

    const int b = blockIdx.y;
    const int tid = threadIdx.x;
    if (tid < GG) {
        const float* t = tgt + (b * GG + tid) * 4;
        float gx = t[0], gy = t[1], gz = t[2], gd = t[3];
        float r2 = 0.5f * gd;
        s_gx[tid] = gx; s_gy[tid] = gy; s_gz[tid] = gz; s_gd[tid] = gd;
        s_gxp[tid] = gx + r2; s_gxm[tid] = gx - r2;
        s_gyp[tid] = gy + r2; s_gym[tid] = gy - r2;
        s_gzp[tid] = gz + r2; s_gzm[tid] = gz - r2;
        s_d3[tid] = gd * gd * gd;
    }
    for (int i = tid; i < 2048; i += blockDim.x) s_hist[i] = 0u;
    __syncthreads();

    const int vox = blockIdx.x * blockDim.x + tid;
    const int w = vox % WWW;
    const int t2 = vox / WWW;
    const int h = t2 % HHH;
    const int d = t2 / HHH;
    const float cx = (float)(w * 4 + 2);
    const float cy = (float)(h * 4 + 2);
    const float cz = (float)(d * 4 + 2);

    const float* p = pred + ((size_t)b * NELEM + (size_t)vox * AAN) * 5;

    const float r1s[3]  = {2.5f, 5.0f, 10.0f};
    const float a3s[3]  = {125.0f, 1000.0f, 8000.0f};
    const float inva[3] = {0.2f, 0.1f, 0.05f};

    float bi[3], bu[3];
    int   bidx[3];
#pragma unroll
    for (int a = 0; a < 3; a++) { bi[a] = -1.0f; bu[a] = 1.0f; bidx[a] = 0; }

#pragma unroll
    for (int g = 0; g < GG; g++) {
        float xp = s_gxp[g], xm = s_gxm[g];
        float yp = s_gyp[g], ym = s_gym[g];
        float zp = s_gzp[g], zm = s_gzm[g];
        float d3 = s_d3[g];
#pragma unroll
        for (int a = 0; a < 3; a++) {
            float r1 = r1s[a];
            float ix = fminf(cx + r1, xp) - fmaxf(cx - r1, xm); ix = fmaxf(ix, 0.0f);
            float iy = fminf(cy + r1, yp) - fmaxf(cy - r1, ym); iy = fmaxf(iy, 0.0f);
            float iz = fminf(cz + r1, zp) - fmaxf(cz - r1, zm); iz = fmaxf(iz, 0.0f);
            float inter = ix * iy * iz;
            float un = a3s[a] + d3 - inter + 1e-6f;
            // iou_g > iou_best  <=>  inter*bu > bi*un  (both denominators > 0)
            if (inter * bu[a] > bi[a] * un) { bi[a] = inter; bu[a] = un; bidx[a] = g; }
        }
    }

    unsigned uout[3];
    float lpos = 0.0f, lreg = 0.0f;
    int lnp = 0;
#pragma unroll
    for (int a = 0; a < 3; a++) {
        float conf = p[a * 5];
        bool pos = bi[a] > 0.5f  * bu[a];
        bool neg = bi[a] < 0.02f * bu[a];
        unsigned u = 0u;
        if (neg) { u = ordmap(conf); atomicAdd(&s_hist[u >> 21], 1u); }
        uout[a] = u;
        if (pos) {
            lnp++;
            lpos += fmaxf(conf, 0.0f) - conf + log1pf(expf(-fabsf(conf)));
            int g = bidx[a];
            float ia = inva[a];
            float tx = (s_gx[g] - cx) * ia;
            float ty = (s_gy[g] - cy) * ia;
            float tz = (s_gz[g] - cz) * ia;
            float td = logf(s_gd[g] * ia);
            lreg += sl1(p[a*5+1] - tx) + sl1(p[a*5+2] - ty)
                  + sl1(p[a*5+3] - tz) + sl1(p[a*5+4] - td);
        }
    }
    unsigned base = (unsigned)b * NELEM + (unsigned)vox * 3u;
    g_u[base]     = uout[0];
    g_u[base + 1] = uout[1];
    g_u[base + 2] = uout[2];
    if (lnp) {
        atomicAdd(&g_pos_sum[b], lpos);
        atomicAdd(&g_reg_sum[b], lreg);
        atomicAdd(&g_npos[b], (unsigned)lnp);
    }
    __syncthreads();
    for (int i = tid; i < 2048; i += blockDim.x) {
        unsigned c = s_hist[i];
        if (c) atomicAdd(&g_hist1[b][i], c);
    }
    __threadfence();
    __syncthreads();
    if (tid == 0) s_last = (atomicAdd(&g_arriveA[b], 1u) == gridDim.x - 1);
    __syncthreads();
    if (!s_last) return;

    // ---- last block of this sample: level-1 selection ----
    if (tid < 32) {
        const int lane = tid;
        const int base1 = 2047 - 64 * lane;       // lane 0 covers the top bins
        unsigned cc = 0;
#pragma unroll 8
        for (int j = 0; j < 64; j++) cc += g_hist1[b][base1 - j];
        unsigned pre = wscan_incl(cc);
        unsigned excl = pre - cc;
        unsigned total = __shfl_sync(0xffffffffu, pre, 31);
        if (total <= KTOP) {
            if (lane == 0) { g_done[b] = 1; g_kcnt[b] = (float)total; }
        } else {
            if (lane == 0) { g_done[b] = 0; g_kcnt[b] = (float)KTOP; }
            bool cross = (excl < KTOP) && (pre >= KTOP);
            unsigned m = __ballot_sync(0xffffffffu, cross);
            int src = __ffs(m) - 1;
            if (lane == src) {
                unsigned c = excl;
                for (int j = 0; j < 64; j++) {
                    unsigned cnt = g_hist1[b][base1 - j];
                    if (c + cnt >= KTOP) { g_b1[b] = base1 - j; g_k2[b] = KTOP - c; break; }
                    c += cnt;
                }
            }
        }
    }
    __syncthreads();
    // self-clean for next launch
    for (int i = tid; i < 2048; i += blockDim.x) g_hist1[b][i] = 0u;
    if (tid == 0) g_arriveA[b] = 0u;
}

// ================= kernel B: refine pass + fused exact in-bin select + final ==
// grid (NELEM/4/256, BB)
__global__ void k_B(float* __restrict__ out) {
    __shared__ unsigned sh2[2048];
    __shared__ unsigned sh3[1024];
    __shared__ float sAcc;
    __shared__ int s_last, s_fin, sb2;
    __shared__ unsigned sk3;

    const int b = blockIdx.y;
    const int tid = threadIdx.x;
    const int done = g_done[b];
    const int b1 = g_b1[b];

    const int i = blockIdx.x * blockDim.x + tid;
    const uint4 v = ((const uint4*)g_u)[(size_t)b * (NELEM / 4) + i];
    unsigned uu[4] = {v.x, v.y, v.z, v.w};
    float s = 0.0f;
#pragma unroll
    for (int j = 0; j < 4; j++) {
        unsigned u = uu[j];
        if (!u) continue;
        if (done) {
            s += softplus0(unord(u));            // total negatives <= KTOP: all counted
        } else {
            int t = (int)(u >> 21);
            if (t > b1) s += softplus0(unord(u)); // strictly-above: < KTOP elements total
            else if (t == b1) {
                unsigned idx = atomicAdd(&g_listn[b], 1u);
                g_list[(size_t)b * NELEM + idx] = u;
            }
        }
    }
#pragma unroll
    for (int off = 16; off; off >>= 1) s += __shfl_down_sync(0xffffffffu, s, off);
    if ((tid & 31) == 0 && s != 0.0f) atomicAdd(&g_topsum[b], s);

    __threadfence();
    __syncthreads();
    if (tid == 0) s_last = (atomicAdd(&g_arriveB[b], 1u) == gridDim.x - 1);
    __syncthreads();
    if (!s_last) return;

    // ---- last block of this sample: exact in-bin top-k2 ----
    const float kcnt = g_kcnt[b];
    if (done) {
        if (tid == 0) g_neg[b] = (kcnt > 0.0f) ? g_topsum[b] / kcnt : 0.0f;
        __syncthreads();
    } else {
        const unsigned k2 = g_k2[b];
        const unsigned n = g_listn[b];
        const unsigned* lst = g_list + (size_t)b * NELEM;

        for (int j = tid; j < 2048; j += blockDim.x) sh2[j] = 0u;
        __syncthreads();
        for (unsigned j = tid; j < n; j += blockDim.x)
            atomicAdd(&sh2[(lst[j] >> 10) & 0x7FFu], 1u);
        __syncthreads();

        if (tid < 32) {                          // warp0: find mid-level crossing
            const int lane = tid;
            const int base2 = 2047 - 64 * lane;
            unsigned cc = 0;
#pragma unroll 8
            for (int j = 0; j < 64; j++) cc += sh2[base2 - j];
            unsigned pre = wscan_incl(cc);
            unsigned excl = pre - cc;
            bool cross = (excl < k2) && (pre >= k2);
            unsigned m = __ballot_sync(0xffffffffu, cross);
            int src = __ffs(m) - 1;
            if (lane == src) {
                unsigned c = excl;
                for (int j = 0; j < 64; j++) {
                    unsigned cnt = sh2[base2 - j];
                    if (c + cnt >= k2) { sb2 = base2 - j; sk3 = k2 - c; break; }
                    c += cnt;
                }
            }
        }
        __syncthreads();
        const int b2 = sb2;

        for (int j = tid; j < 1024; j += blockDim.x) sh3[j] = 0u;
        if (tid == 0) sAcc = 0.0f;
        __syncthreads();

        float s2 = 0.0f;
        for (unsigned j = tid; j < n; j += blockDim.x) {
            unsigned u = lst[j];
            int m = (int)((u >> 10) & 0x7FFu);
            if (m > b2) s2 += softplus0(unord(u));
            else if (m == b2) atomicAdd(&sh3[u & 0x3FFu], 1u);
        }
#pragma unroll
        for (int off = 16; off; off >>= 1) s2 += __shfl_down_sync(0xffffffffu, s2, off);
        if ((tid & 31) == 0 && s2 != 0.0f) atomicAdd(&sAcc, s2);
        __syncthreads();

        if (tid < 32) {                          // warp0: exact-value final bins
            const int lane = tid;
            const unsigned k = sk3;
            const unsigned pref = ((unsigned)b1 << 21) | ((unsigned)b2 << 10);
            const int base3 = 1023 - 32 * lane;
            unsigned cc = 0;
            float ws = 0.0f;
            for (int j = 0; j < 32; j++) {
                unsigned cnt = sh3[base3 - j];
                if (cnt) ws += (float)cnt * softplus0(unord(pref | (unsigned)(base3 - j)));
                cc += cnt;
            }
            unsigned pre = wscan_incl(cc);
            unsigned excl = pre - cc;
            float contrib;
            if (pre <= k) contrib = ws;
            else if (excl >= k) contrib = 0.0f;
            else {
                unsigned c = excl;
                contrib = 0.0f;
                for (int j = 0; j < 32; j++) {
                    unsigned cnt = sh3[base3 - j];
                    if (!cnt) continue;
                    float sp = softplus0(unord(pref | (unsigned)(base3 - j)));
                    if (c + cnt >= k) { contrib += (float)(k - c) * sp; break; }
                    contrib += (float)cnt * sp;
                    c += cnt;
                }
            }
#pragma unroll
            for (int off = 16; off; off >>= 1)
                contrib += __shfl_down_sync(0xffffffffu, contrib, off);
            if (lane == 0) g_neg[b] = (g_topsum[b] + sAcc + contrib) / kcnt;
        }
        __syncthreads();
    }

    // per-sample cleanup, then cross-sample finalize
    if (tid == 0) { g_listn[b] = 0u; g_arriveB[b] = 0u; }
    __threadfence();
    __syncthreads();
    if (tid == 0) s_fin = (atomicAdd(&g_arriveF, 1u) == BB - 1);
    __syncthreads();
    if (s_fin && tid == 0) {
        float cls = 0.0f, reg = 0.0f, npsum = 0.0f;
        for (int bb = 0; bb < BB; bb++) {
            float np = (float)g_npos[bb];
            float pl = (np > 0.0f) ? 5.0f * g_pos_sum[bb] / np : 0.0f;
            float rl = (np > 0.0f) ? g_reg_sum[bb] / (4.0f * np) : 0.0f;
            cls += pl + g_neg[bb];
            reg += rl;
            npsum += np;
            g_pos_sum[bb] = 0.0f; g_reg_sum[bb] = 0.0f;
            g_topsum[bb] = 0.0f;  g_npos[bb] = 0u;
        }
        g_arriveF = 0u;
        cls *= 0.25f;
        reg *= 0.25f;
        out[0] = cls + 0.5f * reg;
        out[1] = cls;
        out[2] = reg;
        out[3] = npsum;
    }
}

// ---------------- launcher ----------------
extern "C" void kernel_launch(void* const* d_in, const int* in_sizes, int n_in,
                              void* d_out, int out_size) {
    const float* pred = (const float*)d_in[0];   // (4,48,48,48,3,5)
    const float* tgt  = (const float*)d_in[1];   // (4,8,4)
    float* out = (float*)d_out;

    dim3 ga(NVOX / 256, BB);        // 432 x 4
    k_A<<<ga, 256>>>(pred, tgt);
    dim3 gb(NELEM / 4 / 256, BB);   // 324 x 4
    k_B<<<gb, 256>>>(out);
}